// round 4
// baseline (speedup 1.0000x reference)
#include <cuda_runtime.h>
#include <cstdint>

// Problem constants
#define NB 4
#define SLEN 32768
#define C1 128
#define C2C 256
#define C3 512
#define L1O 16384
#define L2O 8192
#define L3O 4096
#define VOCAB 2048
#define KCB 4
#define NCODES (KCB * VOCAB)   // 8192
#define MTOT (NB * L3O)        // 16384
#define NT 64                  // 8192/128 n-tiles, 16 per codebook

typedef unsigned long long u64;

// Scratch (device globals: alloc-free). Activation rows padded: stride L+8,
// data at offset +4, 4-float zero guards on both sides (zeroed every call).
__device__ float g_f1p[NB * C1 * (L1O + 8)];     // ~33.6 MB
__device__ float g_f2p[NB * C2C * (L2O + 8)];    // ~33.6 MB
__device__ float g_f3d[NB * C3 * (2 * L3O)];     // 67 MB (duplicated values)
__device__ float g_w2t[C1 * 7 * C2C];            // w2 transposed [CI][7][CO]
__device__ float g_w3t[C2C * 7 * C3];            // w3 transposed [CI][7][CO]
__device__ float g_cbT[512 * NCODES];            // codebook^T [k][n]
__device__ float g_c2[NCODES];
__device__ u64   g_pkey[MTOT * NT];              // 8 MB

// ---------------------------------------------------------------------------
// packed f32x2 helpers (FFMA2 path — PTX only)
// ---------------------------------------------------------------------------
__device__ __forceinline__ void fma2(u64& d, u64 a, u64 b) {
    asm("fma.rn.f32x2 %0, %1, %2, %0;" : "+l"(d) : "l"(a), "l"(b));
}
__device__ __forceinline__ void unpack2(u64 v, float& lo, float& hi) {
    asm("mov.b64 {%0, %1}, %2;" : "=f"(lo), "=f"(hi) : "l"(v));
}
__device__ __forceinline__ u64 dup2(float v) {
    u64 r;
    asm("mov.b64 %0, {%1, %1};" : "=l"(r) : "f"(v));
    return r;
}

// cp.async helpers
__device__ __forceinline__ void cp16(uint32_t dst, const void* src) {
    asm volatile("cp.async.cg.shared.global [%0], [%1], 16;" :: "r"(dst), "l"(src));
}
__device__ __forceinline__ void cp_commit() { asm volatile("cp.async.commit_group;"); }
__device__ __forceinline__ void cp_wait1()  { asm volatile("cp.async.wait_group 1;"); }

// ordered key: (monotonic float bits << 32) | n  -> u64 min == argmin, lowest-idx tie
__device__ __forceinline__ u64 dist_key(float v, int n) {
    unsigned int fb = __float_as_uint(v);
    fb = (fb & 0x80000000u) ? ~fb : (fb | 0x80000000u);
    return ((u64)fb << 32) | (unsigned int)n;
}

// ---------------------------------------------------------------------------
// guard zeroing for padded activation buffers
// ---------------------------------------------------------------------------
__global__ void guard_zero(float* f1p, float* f2p) {
    int i = blockIdx.x * 256 + threadIdx.x;
    int r1 = NB * C1;              // 512 rows
    int r2 = NB * C2C;             // 1024 rows
    if (i < r1 * 8) {
        int row = i >> 3, j = i & 7;
        size_t base = (size_t)row * (L1O + 8);
        f1p[base + (j < 4 ? j : L1O + j)] = 0.0f;   // j>=4 -> 4+L1O+(j-4)
    } else if (i < r1 * 8 + r2 * 8) {
        int k = i - r1 * 8;
        int row = k >> 3, j = k & 7;
        size_t base = (size_t)row * (L2O + 8);
        f2p[base + (j < 4 ? j : L2O + j)] = 0.0f;
    }
}

// ---------------------------------------------------------------------------
// weight transpose: w [CO][CI][7] -> wt [CI][7][CO]
// ---------------------------------------------------------------------------
__global__ void transpose_w(const float* __restrict__ w, float* __restrict__ wt,
                            int CO, int CI) {
    int i = blockIdx.x * 256 + threadIdx.x;
    if (i >= CO * CI * 7) return;
    int co = i / (CI * 7);
    int r  = i % (CI * 7);
    int ci = r / 7, t = r % 7;
    wt[(ci * 7 + t) * CO + co] = w[i];
}

// ---------------------------------------------------------------------------
// conv1: [B,1,32768] -> relu -> padded f1p, k=7, stride=2, pad=3
// ---------------------------------------------------------------------------
__global__ void conv1_kernel(const float* __restrict__ x,
                             const float* __restrict__ w,
                             const float* __restrict__ bias,
                             float* __restrict__ out) {
    int l  = blockIdx.x * 256 + threadIdx.x;
    int co = blockIdx.y;
    int b  = blockIdx.z;
    if (l >= L1O) return;
    const float* xb = x + b * SLEN;
    float acc = bias[co];
#pragma unroll
    for (int t = 0; t < 7; ++t) {
        int g = 2 * l + t - 3;
        float xv = (g >= 0 && g < SLEN) ? xb[g] : 0.0f;
        acc = fmaf(w[co * 7 + t], xv, acc);
    }
    out[((size_t)(b * C1 + co)) * (L1O + 8) + 4 + l] = fmaxf(acc, 0.0f);
}

// ---------------------------------------------------------------------------
// Tiled conv v3 (f32x2): padded input rows (stride L_in+8, offset 4),
// transposed weights [CI][7][CO]. Tile 128L x 128CO, 256 thr, 8x8/thread.
// Input slab stored DUPLICATED as u64 with pad-per-16 (conflict-free LDS.64).
// dup_out=0: write padded rows (stride L_out+8, +relu opt)
// dup_out=1: write duplicated rows (stride 2*L_out, float2 {v,v})
// ---------------------------------------------------------------------------
#define DMAP(j) ((j) + ((j) >> 4))

template <int CI>
__global__ __launch_bounds__(256) void conv_tiled(
        const float* __restrict__ in, const float* __restrict__ wt,
        const float* __restrict__ bias, float* __restrict__ out,
        int L_in, int L_out, int CO, int do_relu, int dup_out) {
    constexpr int TL = 128, TCO = 128, CC = 8;
    __shared__ __align__(16) u64   sInD[CC][278];      // dup'd, DMAP-padded
    __shared__ __align__(16) float sW[CC][7][TCO];

    const int tid = threadIdx.x;
    const int tx = tid & 15;          // l group  (8 outputs)
    const int ty = tid >> 4;          // co group (8 outputs = 4 pairs)
    const int l0  = blockIdx.x * TL;
    const int co0 = blockIdx.y * TCO;
    const int b   = blockIdx.z;
    const int in_base = 2 * l0 - 3;

    u64 acc[8][4];
#pragma unroll
    for (int i = 0; i < 8; ++i)
#pragma unroll
        for (int j = 0; j < 4; ++j) acc[i][j] = 0ull;

    for (int c0 = 0; c0 < CI; c0 += CC) {
        // input slab: 262 floats per ci row, guards make all loads in-bounds
        for (int i = tid; i < CC * 264; i += 256) {
            int ci = i / 264, j = i % 264;
            if (j < 262) {
                float v = in[(size_t)(b * CI + c0 + ci) * (L_in + 8) + 4 + in_base + j];
                sInD[ci][DMAP(j)] = dup2(v);
            }
        }
        // weights: contiguous 128-float runs per (ci,t) from transposed layout
        for (int i = tid; i < CC * 7 * (TCO / 4); i += 256) {
            int ci = i / (7 * 32);
            int r  = i % (7 * 32);
            int t  = r >> 5;
            int c4 = (r & 31) * 4;
            *(float4*)&sW[ci][t][c4] =
                *(const float4*)&wt[(size_t)((c0 + ci) * 7 + t) * CO + co0 + c4];
        }
        __syncthreads();

#pragma unroll
        for (int ci = 0; ci < CC; ++ci) {
#pragma unroll
            for (int t = 0; t < 7; ++t) {
                u64 xd[8];
#pragma unroll
                for (int il = 0; il < 8; ++il) {
                    int j = 16 * tx + 2 * il + t;
                    xd[il] = sInD[ci][DMAP(j)];
                }
                ulonglong2 w0 = *(const ulonglong2*)&sW[ci][t][ty * 8];
                ulonglong2 w1 = *(const ulonglong2*)&sW[ci][t][ty * 8 + 4];
                u64 wv[4] = {w0.x, w0.y, w1.x, w1.y};
#pragma unroll
                for (int il = 0; il < 8; ++il)
#pragma unroll
                    for (int jc = 0; jc < 4; ++jc)
                        fma2(acc[il][jc], xd[il], wv[jc]);
            }
        }
        __syncthreads();
    }

#pragma unroll
    for (int il = 0; il < 8; ++il) {
        int l = l0 + tx * 8 + il;
#pragma unroll
        for (int jc = 0; jc < 4; ++jc) {
            float v0, v1;
            unpack2(acc[il][jc], v0, v1);
            int co = co0 + ty * 8 + jc * 2;
            v0 += bias[co];
            v1 += bias[co + 1];
            if (do_relu) { v0 = fmaxf(v0, 0.0f); v1 = fmaxf(v1, 0.0f); }
            if (!dup_out) {
                out[(size_t)(b * CO + co)     * (L_out + 8) + 4 + l] = v0;
                out[(size_t)(b * CO + co + 1) * (L_out + 8) + 4 + l] = v1;
            } else {
                float2 p0 = {v0, v0}, p1 = {v1, v1};
                *(float2*)&out[(size_t)(b * CO + co)     * (2 * L_out) + 2 * l] = p0;
                *(float2*)&out[(size_t)(b * CO + co + 1) * (2 * L_out) + 2 * l] = p1;
            }
        }
    }
}

// ---------------------------------------------------------------------------
// codebook transpose: cb [8192][512] -> cbT [512][8192]
// ---------------------------------------------------------------------------
__global__ void transpose_cb(const float* __restrict__ cb, float* __restrict__ cbT) {
    __shared__ float t[32][33];
    int k = blockIdx.x * 32 + threadIdx.x;
    int n0 = blockIdx.y * 32;
#pragma unroll
    for (int i = threadIdx.y; i < 32; i += 8)
        t[i][threadIdx.x] = cb[(size_t)(n0 + i) * 512 + k];
    __syncthreads();
    int nt = n0 + threadIdx.x;
    int k0 = blockIdx.x * 32;
#pragma unroll
    for (int i = threadIdx.y; i < 32; i += 8)
        cbT[(size_t)(k0 + i) * NCODES + nt] = t[threadIdx.x][i];
}

// ---------------------------------------------------------------------------
// c2[n] = sum_h codebook[n][h]^2. One warp per row.
// ---------------------------------------------------------------------------
__global__ void c2_kernel(const float* __restrict__ cb, float* __restrict__ c2) {
    int warp = blockIdx.x * 8 + (threadIdx.x >> 5);
    int lane = threadIdx.x & 31;
    if (warp >= NCODES) return;
    const float* row = cb + (size_t)warp * 512;
    float s = 0.0f;
#pragma unroll
    for (int h = lane; h < 512; h += 32) { float v = row[h]; s = fmaf(v, v, s); }
#pragma unroll
    for (int o = 16; o > 0; o >>= 1) s += __shfl_down_sync(0xffffffffu, s, o);
    if (lane == 0) c2[warp] = s;
}

// ---------------------------------------------------------------------------
// Fused VQ GEMM + per-tile argmin (f32x2, cp.async double-buffered).
// A: f3d [B][512][8192] duplicated (m contiguous, dup'd);  B: cbT [512][8192].
// Block tile 128m x 128n, KC=16, 256 threads, 8x8 per thread. Zero packs.
// ---------------------------------------------------------------------------
#define VTM 128
#define VTN 128
#define VKC 16

__global__ __launch_bounds__(256) void vq_gemm(
        const float* __restrict__ f3d, const float* __restrict__ cbT,
        const float* __restrict__ c2, u64* __restrict__ pkey) {
    // 2 x (A dup 16x256 + B 16x128) floats = 48 KB; reused for reduction
    __shared__ __align__(16) char smem_raw[2 * VKC * (2 * VTM + VTN) * 4];
    float* sA = (float*)smem_raw;                                   // [2][VKC][256]
    float* sB = (float*)(smem_raw + 2 * VKC * 2 * VTM * 4);         // [2][VKC][128]
    const uint32_t sA_u = (uint32_t)__cvta_generic_to_shared(sA);
    const uint32_t sB_u = (uint32_t)__cvta_generic_to_shared(sB);

    const int tid = threadIdx.x;
    const int tx = tid & 15;          // n group (8 cols)
    const int ty = tid >> 4;          // m group (8 rows)
    const int m0 = blockIdx.x * VTM;
    const int n0 = blockIdx.y * VTN;
    const int b  = m0 >> 12;
    const int l0 = m0 & 4095;
    const float* Abase = f3d + (size_t)b * 512 * 8192 + 2 * l0;
    const float* Bbase = cbT + n0;

    u64 acc[8][4];
#pragma unroll
    for (int i = 0; i < 8; ++i)
#pragma unroll
        for (int j = 0; j < 4; ++j) acc[i][j] = 0ull;

    // chunk loader: A = 1024 cp16, B = 512 cp16 -> 6 per thread
    auto load_chunk = [&](int c, int buf) {
        int k0 = c * VKC;
#pragma unroll
        for (int r = 0; r < 6; ++r) {
            int i = tid + r * 256;              // 0..1535
            if (i < 1024) {
                int kk = i >> 6, off = (i & 63) * 4;
                cp16(sA_u + (((buf * VKC + kk) * 256 + off) << 2),
                     Abase + (size_t)(k0 + kk) * 8192 + off);
            } else {
                int j = i - 1024;
                int kk = j >> 5, off = (j & 31) * 4;
                cp16(sB_u + (((buf * VKC + kk) * VTN + off) << 2),
                     Bbase + (size_t)(k0 + kk) * NCODES + off);
            }
        }
    };

    load_chunk(0, 0);
    cp_commit();

    const int NCHUNK = 512 / VKC;     // 32
    for (int c = 0; c < NCHUNK; ++c) {
        if (c + 1 < NCHUNK) load_chunk(c + 1, (c + 1) & 1);
        cp_commit();
        cp_wait1();
        __syncthreads();

        const float* Ac = sA + (c & 1) * VKC * 256;
        const float* Bc = sB + (c & 1) * VKC * VTN;
#pragma unroll
        for (int kk = 0; kk < VKC; ++kk) {
            // a: 8 dup'd u64 (16 floats) straight from shared, no packing
            ulonglong2 a0 = *(const ulonglong2*)(Ac + kk * 256 + ty * 16);
            ulonglong2 a1 = *(const ulonglong2*)(Ac + kk * 256 + ty * 16 + 4);
            ulonglong2 a2 = *(const ulonglong2*)(Ac + kk * 256 + ty * 16 + 8);
            ulonglong2 a3 = *(const ulonglong2*)(Ac + kk * 256 + ty * 16 + 12);
            u64 ad[8] = {a0.x, a0.y, a1.x, a1.y, a2.x, a2.y, a3.x, a3.y};
            ulonglong2 b0 = *(const ulonglong2*)(Bc + kk * VTN + tx * 8);
            ulonglong2 b1 = *(const ulonglong2*)(Bc + kk * VTN + tx * 8 + 4);
            u64 bb[4] = {b0.x, b0.y, b1.x, b1.y};
#pragma unroll
            for (int im = 0; im < 8; ++im)
#pragma unroll
                for (int jn = 0; jn < 4; ++jn)
                    fma2(acc[im][jn], ad[im], bb[jn]);
        }
        __syncthreads();
    }

    // epilogue: per-row argmin of c2[n] - 2*cross over this thread's 8 cols
    u64* sRed = (u64*)smem_raw;   // [128][16] = 16 KB (aliases sA, post-sync)
#pragma unroll
    for (int im = 0; im < 8; ++im) {
        int m = ty * 8 + im;
        u64 best = ~0ull;
#pragma unroll
        for (int jn = 0; jn < 4; ++jn) {
            float lo, hi;
            unpack2(acc[im][jn], lo, hi);
            int n = n0 + tx * 8 + jn * 2;
            u64 k0 = dist_key(c2[n]     - 2.0f * lo, n);
            u64 k1 = dist_key(c2[n + 1] - 2.0f * hi, n + 1);
            if (k0 < best) best = k0;
            if (k1 < best) best = k1;
        }
        sRed[m * 16 + tx] = best;
    }
    __syncthreads();

    if (tid < VTM) {
        u64 best = sRed[tid * 16];
#pragma unroll
        for (int j = 1; j < 16; ++j) {
            u64 v = sRed[tid * 16 + j];
            if (v < best) best = v;
        }
        pkey[(size_t)(m0 + tid) * NT + blockIdx.y] = best;
    }
}

// ---------------------------------------------------------------------------
// Finalize: per (b,l) reduce 16 key-partials per codebook -> tokens (float),
// then emb = mean of the 4 embedding rows.
// ---------------------------------------------------------------------------
__global__ void finalize_kernel(const u64* __restrict__ pkey,
                                const float* __restrict__ emb_table,
                                float* __restrict__ out) {
    __shared__ int tok[KCB];
    const int m = blockIdx.x;            // 0..16383
    const int b = m >> 12, l = m & 4095;
    const int tid = threadIdx.x;         // 128 threads

    if (tid < KCB) {
        u64 best = ~0ull;
#pragma unroll
        for (int j = 0; j < 16; ++j) {
            u64 v = pkey[(size_t)m * NT + tid * 16 + j];
            if (v < best) best = v;
        }
        int t = ((int)(best & 0xffffffffu)) & (VOCAB - 1);
        tok[tid] = t;
        out[((size_t)b * KCB + tid) * L3O + l] = (float)t;
    }
    __syncthreads();

    float* out_emb = out + (size_t)NB * KCB * L3O;
    int t0 = tok[0], t1 = tok[1], t2 = tok[2], t3 = tok[3];
    for (int h = tid; h < 512; h += 128) {
        float s = emb_table[(size_t)t0 * 512 + h] + emb_table[(size_t)t1 * 512 + h]
                + emb_table[(size_t)t2 * 512 + h] + emb_table[(size_t)t3 * 512 + h];
        out_emb[((size_t)b * L3O + l) * 512 + h] = 0.25f * s;
    }
}

// ---------------------------------------------------------------------------
extern "C" void kernel_launch(void* const* d_in, const int* in_sizes, int n_in,
                              void* d_out, int out_size) {
    const float* audio = (const float*)d_in[0];
    const float* w1    = (const float*)d_in[1];
    const float* b1    = (const float*)d_in[2];
    const float* w2    = (const float*)d_in[3];
    const float* b2    = (const float*)d_in[4];
    const float* w3    = (const float*)d_in[5];
    const float* b3    = (const float*)d_in[6];
    const float* cb    = (const float*)d_in[7];
    const float* emb   = (const float*)d_in[8];
    float* out = (float*)d_out;

    float *f1p, *f2p, *f3d, *w2t, *w3t, *cbT, *c2p;
    u64* pkey;
    cudaGetSymbolAddress((void**)&f1p,  g_f1p);
    cudaGetSymbolAddress((void**)&f2p,  g_f2p);
    cudaGetSymbolAddress((void**)&f3d,  g_f3d);
    cudaGetSymbolAddress((void**)&w2t,  g_w2t);
    cudaGetSymbolAddress((void**)&w3t,  g_w3t);
    cudaGetSymbolAddress((void**)&cbT,  g_cbT);
    cudaGetSymbolAddress((void**)&c2p,  g_c2);
    cudaGetSymbolAddress((void**)&pkey, g_pkey);

    // prep: guards + transposed weights + codebook prep
    guard_zero<<<((NB * C1 + NB * C2C) * 8 + 255) / 256, 256>>>(f1p, f2p);
    transpose_w<<<(C2C * C1 * 7 + 255) / 256, 256>>>(w2, w2t, C2C, C1);
    transpose_w<<<(C3 * C2C * 7 + 255) / 256, 256>>>(w3, w3t, C3, C2C);
    transpose_cb<<<dim3(512 / 32, NCODES / 32), dim3(32, 8)>>>(cb, cbT);
    c2_kernel<<<NCODES / 8, 256>>>(cb, c2p);

    // conv chain
    conv1_kernel<<<dim3(L1O / 256, C1, NB), 256>>>(audio, w1, b1, f1p);
    conv_tiled<C1><<<dim3(L2O / 128, C2C / 128, NB), 256>>>(
        f1p, w2t, b2, f2p, L1O, L2O, C2C, 1, 0);
    conv_tiled<C2C><<<dim3(L3O / 128, C3 / 128, NB), 256>>>(
        f2p, w3t, b3, f3d, L2O, L3O, C3, 0, 1);

    // VQ GEMM + tile argmin, then tokens + embedding mean
    vq_gemm<<<dim3(MTOT / VTM, NT), 256>>>(f3d, cbT, c2p, pkey);
    finalize_kernel<<<MTOT, 128>>>(pkey, emb, out);
}

// round 5
// speedup vs baseline: 1.2411x; 1.2411x over previous
#include <cuda_runtime.h>
#include <cstdint>

// Problem constants
#define NB 4
#define SLEN 32768
#define C1 128
#define C2C 256
#define C3 512
#define L1O 16384
#define L2O 8192
#define L3O 4096
#define VOCAB 2048
#define KCB 4
#define NCODES (KCB * VOCAB)   // 8192
#define MTOT (NB * L3O)        // 16384
#define NT 64                  // 8192/128 n-tiles, 16 per codebook

typedef unsigned long long u64;

// Activation rows padded: stride L+16, data at offset +8, 8-float zero guards.
__device__ float g_f1p[NB * C1 * (L1O + 16)];
__device__ float g_f2p[NB * C2C * (L2O + 16)];
__device__ float g_f3[NB * C3 * L3O];            // plain layout for vq
__device__ float g_w2t[C1 * 7 * C2C];            // w2^T [CI][7][CO]
__device__ float g_w3t[C2C * 7 * C3];            // w3^T [CI][7][CO]
__device__ float g_cbT[512 * NCODES];            // codebook^T [k][n]
__device__ float g_c2[NCODES];
__device__ u64   g_pkey[MTOT * NT];

// ---------------------------------------------------------------------------
// packed f32x2 helpers (FFMA2 path — PTX only)
// ---------------------------------------------------------------------------
__device__ __forceinline__ void fma2(u64& d, u64 a, u64 b) {
    asm("fma.rn.f32x2 %0, %1, %2, %0;" : "+l"(d) : "l"(a), "l"(b));
}
__device__ __forceinline__ void unpack2(u64 v, float& lo, float& hi) {
    asm("mov.b64 {%0, %1}, %2;" : "=f"(lo), "=f"(hi) : "l"(v));
}
__device__ __forceinline__ u64 pack2(float lo, float hi) {
    u64 r;
    asm("mov.b64 %0, {%1, %2};" : "=l"(r) : "f"(lo), "f"(hi));
    return r;
}
__device__ __forceinline__ u64 dup2(float v) {
    u64 r;
    asm("mov.b64 %0, {%1, %1};" : "=l"(r) : "f"(v));
    return r;
}

// cp.async helpers
__device__ __forceinline__ void cp16(uint32_t dst, const void* src) {
    asm volatile("cp.async.cg.shared.global [%0], [%1], 16;" :: "r"(dst), "l"(src));
}
__device__ __forceinline__ void cp_commit() { asm volatile("cp.async.commit_group;"); }
__device__ __forceinline__ void cp_wait0()  { asm volatile("cp.async.wait_group 0;"); }

// ordered key: (monotonic float bits << 32) | n -> u64 min == argmin, lowest-idx tie
__device__ __forceinline__ u64 dist_key(float v, int n) {
    unsigned int fb = __float_as_uint(v);
    fb = (fb & 0x80000000u) ? ~fb : (fb | 0x80000000u);
    return ((u64)fb << 32) | (unsigned int)n;
}

// ---------------------------------------------------------------------------
// guard zeroing for padded activation buffers (16 floats per row)
// ---------------------------------------------------------------------------
__global__ void guard_zero(float* f1p, float* f2p) {
    int i = blockIdx.x * 256 + threadIdx.x;
    const int r1 = NB * C1;              // 512 rows
    const int r2 = NB * C2C;             // 1024 rows
    if (i < r1 * 16) {
        int row = i >> 4, j = i & 15;
        size_t base = (size_t)row * (L1O + 16);
        f1p[base + (j < 8 ? j : L1O + j)] = 0.0f;   // j>=8 -> 8+L1O+(j-8)
    } else if (i < r1 * 16 + r2 * 16) {
        int k = i - r1 * 16;
        int row = k >> 4, j = k & 15;
        size_t base = (size_t)row * (L2O + 16);
        f2p[base + (j < 8 ? j : L2O + j)] = 0.0f;
    }
}

// ---------------------------------------------------------------------------
// weight transpose: w [CO][CI][7] -> wt [CI][7][CO]
// ---------------------------------------------------------------------------
__global__ void transpose_w(const float* __restrict__ w, float* __restrict__ wt,
                            int CO, int CI) {
    int i = blockIdx.x * 256 + threadIdx.x;
    if (i >= CO * CI * 7) return;
    int co = i / (CI * 7);
    int r  = i % (CI * 7);
    int ci = r / 7, t = r % 7;
    wt[(ci * 7 + t) * CO + co] = w[i];
}

// ---------------------------------------------------------------------------
// conv1: [B,1,32768] -> relu -> padded f1p, k=7, stride=2, pad=3
// ---------------------------------------------------------------------------
__global__ void conv1_kernel(const float* __restrict__ x,
                             const float* __restrict__ w,
                             const float* __restrict__ bias,
                             float* __restrict__ out) {
    int l  = blockIdx.x * 256 + threadIdx.x;
    int co = blockIdx.y;
    int b  = blockIdx.z;
    if (l >= L1O) return;
    const float* xb = x + b * SLEN;
    float acc = bias[co];
#pragma unroll
    for (int t = 0; t < 7; ++t) {
        int g = 2 * l + t - 3;
        float xv = (g >= 0 && g < SLEN) ? xb[g] : 0.0f;
        acc = fmaf(w[co * 7 + t], xv, acc);
    }
    out[(size_t)(b * C1 + co) * (L1O + 16) + 8 + l] = fmaxf(acc, 0.0f);
}

// ---------------------------------------------------------------------------
// Tiled conv v4 (f32x2, double-buffered): padded input rows (stride L_in+16,
// offset 8), transposed weights [CI][7][CO] via cp.async.
// Tile 128L x 128CO, 256 thr, 8x8 per thread. CC=4 ci per chunk.
// Slab stored duplicated u64 with +1-per-16 pad (conflict-free LDS.64).
// ---------------------------------------------------------------------------
#define DMAP(j) ((j) + ((j) >> 4))

template <int CI>
__global__ __launch_bounds__(256, 2) void conv_tiled(
        const float* __restrict__ in, const float* __restrict__ wt,
        const float* __restrict__ bias, float* __restrict__ out,
        int L_in, int L_out, int CO, int do_relu, int out_stride, int out_off) {
    constexpr int TL = 128, TCO = 128, CC = 4;
    __shared__ __align__(16) u64   sInD[2][CC][286];      // DMAP(267)=283 max
    __shared__ __align__(16) float sW[2][CC][7][TCO];
    const uint32_t sW_u = (uint32_t)__cvta_generic_to_shared(&sW[0][0][0][0]);

    const int tid = threadIdx.x;
    const int tx = tid & 15;          // l group  (8 outputs)
    const int ty = tid >> 4;          // co group (8 outputs = 4 pairs)
    const int l0  = blockIdx.x * TL;
    const int co0 = blockIdx.y * TCO;
    const int b   = blockIdx.z;
    // slab origin s0 = 2*l0 - 4 (16B aligned); logical j -> slab index j+1
    const float* slab_base = in + 8 + (2 * l0 - 4);

    u64 acc[8][4];
#pragma unroll
    for (int i = 0; i < 8; ++i)
#pragma unroll
        for (int j = 0; j < 4; ++j) acc[i][j] = 0ull;

    // slab: CC rows x 268 floats (67 float4) -> dup'd u64, DMAP'd
    auto load_slab = [&](int c0, int buf) {
        for (int i = tid; i < CC * 67; i += 256) {
            int ci = i / 67, q = i % 67;
            const float* p = slab_base + (size_t)(b * CI + c0 + ci) * (L_in + 16) + q * 4;
            float4 v = *(const float4*)p;
            u64* d = &sInD[buf][ci][DMAP(q * 4)];
            d[0] = dup2(v.x); d[1] = dup2(v.y); d[2] = dup2(v.z); d[3] = dup2(v.w);
        }
    };
    // weights: CC*7 contiguous 128-float runs via cp.async
    auto load_w = [&](int c0, int buf) {
        for (int i = tid; i < CC * 7 * (TCO / 4); i += 256) {
            int ci = i / (7 * 32);
            int r  = i % (7 * 32);
            int t  = r >> 5;
            int c4 = (r & 31) * 4;
            uint32_t off = ((((buf * CC + ci) * 7 + t) * TCO) + c4) * 4;
            cp16(sW_u + off, &wt[(size_t)((c0 + ci) * 7 + t) * CO + co0 + c4]);
        }
    };

    load_slab(0, 0);
    load_w(0, 0);
    cp_commit();

    const int NCH = CI / CC;
    for (int c = 0; c < NCH; ++c) {
        const int buf = c & 1;
        cp_wait0();
        __syncthreads();                      // loads(c) visible, compute(c-1) done
        if (c + 1 < NCH) {
            load_slab((c + 1) * CC, buf ^ 1);
            load_w((c + 1) * CC, buf ^ 1);
            cp_commit();
        }
#pragma unroll
        for (int ci = 0; ci < CC; ++ci) {
#pragma unroll
            for (int t = 0; t < 7; ++t) {
                u64 xd[8];
#pragma unroll
                for (int il = 0; il < 8; ++il) {
                    int j = 16 * tx + 2 * il + t + 1;   // +1: slab origin shift
                    xd[il] = sInD[buf][ci][DMAP(j)];
                }
                ulonglong2 w0 = *(const ulonglong2*)&sW[buf][ci][t][ty * 8];
                ulonglong2 w1 = *(const ulonglong2*)&sW[buf][ci][t][ty * 8 + 4];
                u64 wv[4] = {w0.x, w0.y, w1.x, w1.y};
#pragma unroll
                for (int il = 0; il < 8; ++il)
#pragma unroll
                    for (int jc = 0; jc < 4; ++jc)
                        fma2(acc[il][jc], xd[il], wv[jc]);
            }
        }
    }

#pragma unroll
    for (int il = 0; il < 8; ++il) {
        int l = l0 + tx * 8 + il;
#pragma unroll
        for (int jc = 0; jc < 4; ++jc) {
            float v0, v1;
            unpack2(acc[il][jc], v0, v1);
            int co = co0 + ty * 8 + jc * 2;
            v0 += bias[co];
            v1 += bias[co + 1];
            if (do_relu) { v0 = fmaxf(v0, 0.0f); v1 = fmaxf(v1, 0.0f); }
            out[(size_t)(b * CO + co)     * out_stride + out_off + l] = v0;
            out[(size_t)(b * CO + co + 1) * out_stride + out_off + l] = v1;
        }
    }
}

// ---------------------------------------------------------------------------
// codebook transpose: cb [8192][512] -> cbT [512][8192]
// ---------------------------------------------------------------------------
__global__ void transpose_cb(const float* __restrict__ cb, float* __restrict__ cbT) {
    __shared__ float t[32][33];
    int k = blockIdx.x * 32 + threadIdx.x;
    int n0 = blockIdx.y * 32;
#pragma unroll
    for (int i = threadIdx.y; i < 32; i += 8)
        t[i][threadIdx.x] = cb[(size_t)(n0 + i) * 512 + k];
    __syncthreads();
    int nt = n0 + threadIdx.x;
    int k0 = blockIdx.x * 32;
#pragma unroll
    for (int i = threadIdx.y; i < 32; i += 8)
        cbT[(size_t)(k0 + i) * NCODES + nt] = t[threadIdx.x][i];
}

// ---------------------------------------------------------------------------
// c2[n] = sum_h codebook[n][h]^2. One warp per row.
// ---------------------------------------------------------------------------
__global__ void c2_kernel(const float* __restrict__ cb, float* __restrict__ c2) {
    int warp = blockIdx.x * 8 + (threadIdx.x >> 5);
    int lane = threadIdx.x & 31;
    if (warp >= NCODES) return;
    const float* row = cb + (size_t)warp * 512;
    float s = 0.0f;
#pragma unroll
    for (int h = lane; h < 512; h += 32) { float v = row[h]; s = fmaf(v, v, s); }
#pragma unroll
    for (int o = 16; o > 0; o >>= 1) s += __shfl_down_sync(0xffffffffu, s, o);
    if (lane == 0) c2[warp] = s;
}

// ---------------------------------------------------------------------------
// Fused VQ GEMM + per-tile argmin (f32x2, cp.async double-buffered).
// A: f3 [B][512][4096] (k-major, m contiguous);  B: cbT [512][8192].
// Block tile 128m x 128n, KC=16, 256 threads, 8x8 per thread.
// ---------------------------------------------------------------------------
#define VTM 128
#define VTN 128
#define VKC 16

__global__ __launch_bounds__(256, 2) void vq_gemm(
        const float* __restrict__ f3, const float* __restrict__ cbT,
        const float* __restrict__ c2, u64* __restrict__ pkey) {
    // 2 buffers x (A 16x128 + B 16x128) floats = 32 KB; reused for reduction
    __shared__ __align__(16) char smem_raw[2 * VKC * (VTM + VTN) * 4];
    float* sA = (float*)smem_raw;                               // [2][VKC][VTM]
    float* sB = (float*)(smem_raw + 2 * VKC * VTM * 4);         // [2][VKC][VTN]
    const uint32_t sA_u = (uint32_t)__cvta_generic_to_shared(sA);
    const uint32_t sB_u = (uint32_t)__cvta_generic_to_shared(sB);

    const int tid = threadIdx.x;
    const int tx = tid & 15;          // n group (8 cols)
    const int ty = tid >> 4;          // m group (8 rows)
    const int m0 = blockIdx.x * VTM;
    const int n0 = blockIdx.y * VTN;
    const int b  = m0 >> 12;
    const int l0 = m0 & 4095;
    const float* Abase = f3 + (size_t)b * 512 * 4096 + l0;
    const float* Bbase = cbT + n0;

    u64 acc[8][4];
#pragma unroll
    for (int i = 0; i < 8; ++i)
#pragma unroll
        for (int j = 0; j < 4; ++j) acc[i][j] = 0ull;

    auto load_chunk = [&](int c, int buf) {
        int k0 = c * VKC;
#pragma unroll
        for (int r = 0; r < 2; ++r) {
            int i = tid + r * 256;            // 0..511
            int kk = i >> 5;
            int off = (i & 31) * 4;
            cp16(sA_u + (((buf * VKC + kk) * VTM + off) << 2),
                 Abase + (size_t)(k0 + kk) * 4096 + off);
            cp16(sB_u + (((buf * VKC + kk) * VTN + off) << 2),
                 Bbase + (size_t)(k0 + kk) * NCODES + off);
        }
    };

    load_chunk(0, 0);
    cp_commit();

    const int NCHUNK = 512 / VKC;     // 32
    for (int c = 0; c < NCHUNK; ++c) {
        cp_wait0();
        __syncthreads();                      // loads(c) visible, compute(c-1) done
        if (c + 1 < NCHUNK) {
            load_chunk(c + 1, (c + 1) & 1);
            cp_commit();
        }
        const float* Ac = sA + (c & 1) * VKC * VTM;
        const float* Bc = sB + (c & 1) * VKC * VTN;
#pragma unroll
        for (int kk = 0; kk < VKC; ++kk) {
            float4 a0 = *(const float4*)(Ac + kk * VTM + ty * 8);
            float4 a1 = *(const float4*)(Ac + kk * VTM + ty * 8 + 4);
            ulonglong2 b0 = *(const ulonglong2*)(Bc + kk * VTN + tx * 8);
            ulonglong2 b1 = *(const ulonglong2*)(Bc + kk * VTN + tx * 8 + 4);
            u64 bb[4] = {b0.x, b0.y, b1.x, b1.y};
            float av[8] = {a0.x, a0.y, a0.z, a0.w, a1.x, a1.y, a1.z, a1.w};
#pragma unroll
            for (int im = 0; im < 8; ++im) {
                u64 ad = dup2(av[im]);
#pragma unroll
                for (int jn = 0; jn < 4; ++jn) fma2(acc[im][jn], ad, bb[jn]);
            }
        }
    }
    __syncthreads();                          // compute done before smem reuse

    // epilogue: per-row argmin of c2[n] - 2*cross over this thread's 8 cols
    u64* sRed = (u64*)smem_raw;               // [128][16] = 16 KB
#pragma unroll
    for (int im = 0; im < 8; ++im) {
        int m = ty * 8 + im;
        u64 best = ~0ull;
#pragma unroll
        for (int jn = 0; jn < 4; ++jn) {
            float lo, hi;
            unpack2(acc[im][jn], lo, hi);
            int n = n0 + tx * 8 + jn * 2;
            u64 k0 = dist_key(c2[n]     - 2.0f * lo, n);
            u64 k1 = dist_key(c2[n + 1] - 2.0f * hi, n + 1);
            if (k0 < best) best = k0;
            if (k1 < best) best = k1;
        }
        sRed[m * 16 + tx] = best;
    }
    __syncthreads();

    if (tid < VTM) {
        u64 best = sRed[tid * 16];
#pragma unroll
        for (int j = 1; j < 16; ++j) {
            u64 v = sRed[tid * 16 + j];
            if (v < best) best = v;
        }
        pkey[(size_t)(m0 + tid) * NT + blockIdx.y] = best;
    }
}

// ---------------------------------------------------------------------------
// Finalize: per (b,l) reduce 16 key-partials per codebook -> tokens (float),
// then emb = mean of the 4 embedding rows.
// ---------------------------------------------------------------------------
__global__ void finalize_kernel(const u64* __restrict__ pkey,
                                const float* __restrict__ emb_table,
                                float* __restrict__ out) {
    __shared__ int tok[KCB];
    const int m = blockIdx.x;            // 0..16383
    const int b = m >> 12, l = m & 4095;
    const int tid = threadIdx.x;         // 128 threads

    if (tid < KCB) {
        u64 best = ~0ull;
#pragma unroll
        for (int j = 0; j < 16; ++j) {
            u64 v = pkey[(size_t)m * NT + tid * 16 + j];
            if (v < best) best = v;
        }
        int t = ((int)(best & 0xffffffffu)) & (VOCAB - 1);
        tok[tid] = t;
        out[((size_t)b * KCB + tid) * L3O + l] = (float)t;
    }
    __syncthreads();

    float* out_emb = out + (size_t)NB * KCB * L3O;
    int t0 = tok[0], t1 = tok[1], t2 = tok[2], t3 = tok[3];
    for (int h = tid; h < 512; h += 128) {
        float s = emb_table[(size_t)t0 * 512 + h] + emb_table[(size_t)t1 * 512 + h]
                + emb_table[(size_t)t2 * 512 + h] + emb_table[(size_t)t3 * 512 + h];
        out_emb[((size_t)b * L3O + l) * 512 + h] = 0.25f * s;
    }
}

// ---------------------------------------------------------------------------
extern "C" void kernel_launch(void* const* d_in, const int* in_sizes, int n_in,
                              void* d_out, int out_size) {
    const float* audio = (const float*)d_in[0];
    const float* w1    = (const float*)d_in[1];
    const float* b1    = (const float*)d_in[2];
    const float* w2    = (const float*)d_in[3];
    const float* b2    = (const float*)d_in[4];
    const float* w3    = (const float*)d_in[5];
    const float* b3    = (const float*)d_in[6];
    const float* cb    = (const float*)d_in[7];
    const float* emb   = (const float*)d_in[8];
    float* out = (float*)d_out;

    float *f1p, *f2p, *f3, *w2t, *w3t, *cbT, *c2p;
    u64* pkey;
    cudaGetSymbolAddress((void**)&f1p,  g_f1p);
    cudaGetSymbolAddress((void**)&f2p,  g_f2p);
    cudaGetSymbolAddress((void**)&f3,   g_f3);
    cudaGetSymbolAddress((void**)&w2t,  g_w2t);
    cudaGetSymbolAddress((void**)&w3t,  g_w3t);
    cudaGetSymbolAddress((void**)&cbT,  g_cbT);
    cudaGetSymbolAddress((void**)&c2p,  g_c2);
    cudaGetSymbolAddress((void**)&pkey, g_pkey);

    // prep: guards + transposed weights + codebook prep
    guard_zero<<<((NB * C1 + NB * C2C) * 16 + 255) / 256, 256>>>(f1p, f2p);
    transpose_w<<<(C2C * C1 * 7 + 255) / 256, 256>>>(w2, w2t, C2C, C1);
    transpose_w<<<(C3 * C2C * 7 + 255) / 256, 256>>>(w3, w3t, C3, C2C);
    transpose_cb<<<dim3(512 / 32, NCODES / 32), dim3(32, 8)>>>(cb, cbT);
    c2_kernel<<<NCODES / 8, 256>>>(cb, c2p);

    // conv chain
    conv1_kernel<<<dim3(L1O / 256, C1, NB), 256>>>(audio, w1, b1, f1p);
    conv_tiled<C1><<<dim3(L2O / 128, C2C / 128, NB), 256>>>(
        f1p, w2t, b2, f2p, L1O, L2O, C2C, 1, L2O + 16, 8);
    conv_tiled<C2C><<<dim3(L3O / 128, C3 / 128, NB), 256>>>(
        f2p, w3t, b3, f3, L2O, L3O, C3, 0, L3O, 0);

    // VQ GEMM + tile argmin, then tokens + embedding mean
    vq_gemm<<<dim3(MTOT / VTM, NT), 256>>>(f3, cbT, c2p, pkey);
    finalize_kernel<<<MTOT, 128>>>(pkey, emb, out);
}

// round 7
// speedup vs baseline: 2.1057x; 1.6966x over previous
#include <cuda_runtime.h>
#include <cuda_bf16.h>
#include <cstdint>

// Problem constants
#define NB 4
#define SLEN 32768
#define C1 128
#define C2C 256
#define C3 512
#define L1O 16384
#define L2O 8192
#define L3O 4096
#define VOCAB 2048
#define KCB 4
#define NCODES (KCB * VOCAB)   // 8192
#define MTOT (NB * L3O)        // 16384
#define NT 64                  // 8192/128 n-tiles, 16 per codebook

typedef unsigned long long u64;

// Activation rows padded: stride L+16, data at offset +8, 8-float zero guards.
__device__ float g_f1p[NB * C1 * (L1O + 16)];
__device__ float g_f2p[NB * C2C * (L2O + 16)];
__device__ float g_f3[NB * C3 * L3O];            // [b][k][l] fp32
__device__ float g_w2t[C1 * 7 * C2C];            // w2^T [CI][7][CO]
__device__ float g_w3t[C2C * 7 * C3];            // w3^T [CI][7][CO]
// bf16 split operands (16B-aligned backing)
__device__ ulonglong2 g_Ah[MTOT * 512 / 8];      // feats hi  [m][k] bf16
__device__ ulonglong2 g_Al[MTOT * 512 / 8];      // feats lo
__device__ ulonglong2 g_Bh[NCODES * 512 / 8];    // codes hi  [n][k] bf16
__device__ ulonglong2 g_Bl[NCODES * 512 / 8];    // codes lo
__device__ float g_c2[NCODES];
__device__ u64   g_pkey[MTOT * NT];

// ---------------------------------------------------------------------------
// packed f32x2 helpers (FFMA2 path — PTX only) for the convs
// ---------------------------------------------------------------------------
__device__ __forceinline__ void fma2(u64& d, u64 a, u64 b) {
    asm("fma.rn.f32x2 %0, %1, %2, %0;" : "+l"(d) : "l"(a), "l"(b));
}
__device__ __forceinline__ void unpack2(u64 v, float& lo, float& hi) {
    asm("mov.b64 {%0, %1}, %2;" : "=f"(lo), "=f"(hi) : "l"(v));
}
__device__ __forceinline__ u64 dup2(float v) {
    u64 r;
    asm("mov.b64 %0, {%1, %1};" : "=l"(r) : "f"(v));
    return r;
}

// cp.async helpers
__device__ __forceinline__ void cp16(uint32_t dst, const void* src) {
    asm volatile("cp.async.cg.shared.global [%0], [%1], 16;" :: "r"(dst), "l"(src));
}
__device__ __forceinline__ void cp_commit() { asm volatile("cp.async.commit_group;"); }
__device__ __forceinline__ void cp_wait0()  { asm volatile("cp.async.wait_group 0;"); }

__device__ __forceinline__ uint32_t smem_u32(const void* p) {
    return (uint32_t)__cvta_generic_to_shared(p);
}

// ordered key: (monotonic float bits << 32) | n -> u64 min == argmin, lowest-idx tie
__device__ __forceinline__ u64 dist_key(float v, int n) {
    unsigned int fb = __float_as_uint(v);
    fb = (fb & 0x80000000u) ? ~fb : (fb | 0x80000000u);
    return ((u64)fb << 32) | (unsigned int)n;
}

// ldmatrix x4 (non-trans)
__device__ __forceinline__ void ldm4(uint32_t* r, uint32_t addr) {
    asm volatile("ldmatrix.sync.aligned.m8n8.x4.shared.b16 {%0,%1,%2,%3}, [%4];"
                 : "=r"(r[0]), "=r"(r[1]), "=r"(r[2]), "=r"(r[3]) : "r"(addr));
}
// mma m16n8k16 row.col bf16 -> f32
__device__ __forceinline__ void mma16816(float* c, const uint32_t* a,
                                         uint32_t b0, uint32_t b1) {
    asm volatile(
        "mma.sync.aligned.m16n8k16.row.col.f32.bf16.bf16.f32 "
        "{%0,%1,%2,%3}, {%4,%5,%6,%7}, {%8,%9}, {%0,%1,%2,%3};"
        : "+f"(c[0]), "+f"(c[1]), "+f"(c[2]), "+f"(c[3])
        : "r"(a[0]), "r"(a[1]), "r"(a[2]), "r"(a[3]), "r"(b0), "r"(b1));
}

// smem row swizzle (rows of 32 bf16 = 4 x 16B chunks)
__device__ __forceinline__ int swz(int row, int c) {
    return row * 64 + ((c ^ ((row & 3) ^ ((row >> 2) & 1))) << 4);
}

// ---------------------------------------------------------------------------
// guard zeroing for padded activation buffers (16 floats per row)
// ---------------------------------------------------------------------------
__global__ void guard_zero(float* f1p, float* f2p) {
    int i = blockIdx.x * 256 + threadIdx.x;
    const int r1 = NB * C1;
    const int r2 = NB * C2C;
    if (i < r1 * 16) {
        int row = i >> 4, j = i & 15;
        size_t base = (size_t)row * (L1O + 16);
        f1p[base + (j < 8 ? j : L1O + j)] = 0.0f;
    } else if (i < r1 * 16 + r2 * 16) {
        int k = i - r1 * 16;
        int row = k >> 4, j = k & 15;
        size_t base = (size_t)row * (L2O + 16);
        f2p[base + (j < 8 ? j : L2O + j)] = 0.0f;
    }
}

// ---------------------------------------------------------------------------
// weight transpose: w [CO][CI][7] -> wt [CI][7][CO]
// ---------------------------------------------------------------------------
__global__ void transpose_w(const float* __restrict__ w, float* __restrict__ wt,
                            int CO, int CI) {
    int i = blockIdx.x * 256 + threadIdx.x;
    if (i >= CO * CI * 7) return;
    int co = i / (CI * 7);
    int r  = i % (CI * 7);
    int ci = r / 7, t = r % 7;
    wt[(ci * 7 + t) * CO + co] = w[i];
}

// ---------------------------------------------------------------------------
// conv1: [B,1,32768] -> relu -> padded f1p, k=7, stride=2, pad=3
// ---------------------------------------------------------------------------
__global__ void conv1_kernel(const float* __restrict__ x,
                             const float* __restrict__ w,
                             const float* __restrict__ bias,
                             float* __restrict__ out) {
    int l  = blockIdx.x * 256 + threadIdx.x;
    int co = blockIdx.y;
    int b  = blockIdx.z;
    if (l >= L1O) return;
    const float* xb = x + b * SLEN;
    float acc = bias[co];
#pragma unroll
    for (int t = 0; t < 7; ++t) {
        int g = 2 * l + t - 3;
        float xv = (g >= 0 && g < SLEN) ? xb[g] : 0.0f;
        acc = fmaf(w[co * 7 + t], xv, acc);
    }
    out[(size_t)(b * C1 + co) * (L1O + 16) + 8 + l] = fmaxf(acc, 0.0f);
}

// ---------------------------------------------------------------------------
// Tiled conv v4 (unchanged from R5)
// ---------------------------------------------------------------------------
#define DMAP(j) ((j) + ((j) >> 4))

template <int CI>
__global__ __launch_bounds__(256, 2) void conv_tiled(
        const float* __restrict__ in, const float* __restrict__ wt,
        const float* __restrict__ bias, float* __restrict__ out,
        int L_in, int L_out, int CO, int do_relu, int out_stride, int out_off) {
    constexpr int TL = 128, TCO = 128, CC = 4;
    __shared__ __align__(16) u64   sInD[2][CC][286];
    __shared__ __align__(16) float sW[2][CC][7][TCO];
    const uint32_t sW_u = smem_u32(&sW[0][0][0][0]);

    const int tid = threadIdx.x;
    const int tx = tid & 15;
    const int ty = tid >> 4;
    const int l0  = blockIdx.x * TL;
    const int co0 = blockIdx.y * TCO;
    const int b   = blockIdx.z;
    const float* slab_base = in + 8 + (2 * l0 - 4);

    u64 acc[8][4];
#pragma unroll
    for (int i = 0; i < 8; ++i)
#pragma unroll
        for (int j = 0; j < 4; ++j) acc[i][j] = 0ull;

    auto load_slab = [&](int c0, int buf) {
        for (int i = tid; i < CC * 67; i += 256) {
            int ci = i / 67, q = i % 67;
            const float* p = slab_base + (size_t)(b * CI + c0 + ci) * (L_in + 16) + q * 4;
            float4 v = *(const float4*)p;
            u64* d = &sInD[buf][ci][DMAP(q * 4)];
            d[0] = dup2(v.x); d[1] = dup2(v.y); d[2] = dup2(v.z); d[3] = dup2(v.w);
        }
    };
    auto load_w = [&](int c0, int buf) {
        for (int i = tid; i < CC * 7 * (TCO / 4); i += 256) {
            int ci = i / (7 * 32);
            int r  = i % (7 * 32);
            int t  = r >> 5;
            int c4 = (r & 31) * 4;
            uint32_t off = ((((buf * CC + ci) * 7 + t) * TCO) + c4) * 4;
            cp16(sW_u + off, &wt[(size_t)((c0 + ci) * 7 + t) * CO + co0 + c4]);
        }
    };

    load_slab(0, 0);
    load_w(0, 0);
    cp_commit();

    const int NCH = CI / CC;
    for (int c = 0; c < NCH; ++c) {
        const int buf = c & 1;
        cp_wait0();
        __syncthreads();
        if (c + 1 < NCH) {
            load_slab((c + 1) * CC, buf ^ 1);
            load_w((c + 1) * CC, buf ^ 1);
            cp_commit();
        }
#pragma unroll
        for (int ci = 0; ci < CC; ++ci) {
#pragma unroll
            for (int t = 0; t < 7; ++t) {
                u64 xd[8];
#pragma unroll
                for (int il = 0; il < 8; ++il) {
                    int j = 16 * tx + 2 * il + t + 1;
                    xd[il] = sInD[buf][ci][DMAP(j)];
                }
                ulonglong2 w0 = *(const ulonglong2*)&sW[buf][ci][t][ty * 8];
                ulonglong2 w1 = *(const ulonglong2*)&sW[buf][ci][t][ty * 8 + 4];
                u64 wv[4] = {w0.x, w0.y, w1.x, w1.y};
#pragma unroll
                for (int il = 0; il < 8; ++il)
#pragma unroll
                    for (int jc = 0; jc < 4; ++jc)
                        fma2(acc[il][jc], xd[il], wv[jc]);
            }
        }
    }

#pragma unroll
    for (int il = 0; il < 8; ++il) {
        int l = l0 + tx * 8 + il;
#pragma unroll
        for (int jc = 0; jc < 4; ++jc) {
            float v0, v1;
            unpack2(acc[il][jc], v0, v1);
            int co = co0 + ty * 8 + jc * 2;
            v0 += bias[co];
            v1 += bias[co + 1];
            if (do_relu) { v0 = fmaxf(v0, 0.0f); v1 = fmaxf(v1, 0.0f); }
            out[(size_t)(b * CO + co)     * out_stride + out_off + l] = v0;
            out[(size_t)(b * CO + co + 1) * out_stride + out_off + l] = v1;
        }
    }
}

// ---------------------------------------------------------------------------
// c2[n] = sum_h codebook[n][h]^2 (exact fp32). One warp per row.
// ---------------------------------------------------------------------------
__global__ void c2_kernel(const float* __restrict__ cb, float* __restrict__ c2) {
    int warp = blockIdx.x * 8 + (threadIdx.x >> 5);
    int lane = threadIdx.x & 31;
    if (warp >= NCODES) return;
    const float* row = cb + (size_t)warp * 512;
    float s = 0.0f;
#pragma unroll
    for (int h = lane; h < 512; h += 32) { float v = row[h]; s = fmaf(v, v, s); }
#pragma unroll
    for (int o = 16; o > 0; o >>= 1) s += __shfl_down_sync(0xffffffffu, s, o);
    if (lane == 0) c2[warp] = s;
}

// ---------------------------------------------------------------------------
// split codebook: cb [8192][512] fp32 -> Bh/Bl [n][k] bf16 (hi + residual)
// ---------------------------------------------------------------------------
__global__ void split_B(const float* __restrict__ cb,
                        __nv_bfloat16* __restrict__ bh,
                        __nv_bfloat16* __restrict__ bl) {
    int i = blockIdx.x * 256 + threadIdx.x;
    if (i >= NCODES * 512) return;
    float v = cb[i];
    __nv_bfloat16 h = __float2bfloat16(v);
    bh[i] = h;
    bl[i] = __float2bfloat16(v - __bfloat162float(h));
}

// ---------------------------------------------------------------------------
// split+transpose feats: f3 [b][k][l] fp32 -> Ah/Al [b*4096+l][k] bf16
// ---------------------------------------------------------------------------
__global__ void split_A(const float* __restrict__ f3,
                        __nv_bfloat16* __restrict__ ah,
                        __nv_bfloat16* __restrict__ al) {
    __shared__ float t[32][33];
    const int b  = blockIdx.z;
    const int k0 = blockIdx.x * 32;
    const int l0 = blockIdx.y * 32;
    for (int i = threadIdx.y; i < 32; i += 8)
        t[i][threadIdx.x] = f3[((size_t)b * 512 + k0 + i) * 4096 + l0 + threadIdx.x];
    __syncthreads();
    for (int i = threadIdx.y; i < 32; i += 8) {
        float v = t[threadIdx.x][i];                 // k = k0+tx, l = l0+i
        __nv_bfloat16 h = __float2bfloat16(v);
        size_t o = ((size_t)b * 4096 + l0 + i) * 512 + k0 + threadIdx.x;
        ah[o] = h;
        al[o] = __float2bfloat16(v - __bfloat162float(h));
    }
}

// ---------------------------------------------------------------------------
// mma.sync VQ GEMM + argmin.
// Block: 128m x 128n, 8 warps = 4(m) x 2(n); warp tile 32m x 64n.
// cross = Ah*Bh + Ah*Bl + Al*Bh (bf16 split-2; AlBl term negligible).
// KC=32 chunks, double-buffered cp.async. smem/buf: Ah|Al|Bh|Bl 8KB each.
// ---------------------------------------------------------------------------
__global__ __launch_bounds__(256, 2) void vq_mma(
        const __nv_bfloat16* __restrict__ Ah, const __nv_bfloat16* __restrict__ Al,
        const __nv_bfloat16* __restrict__ Bh, const __nv_bfloat16* __restrict__ Bl,
        const float* __restrict__ c2, u64* __restrict__ pkey) {
    extern __shared__ __align__(16) char dsm[];          // 2 * 32 KB
    __shared__ u64 sRed[128][2];

    const int tid  = threadIdx.x;
    const int lane = tid & 31;
    const int wid  = tid >> 5;
    const int wm   = wid >> 1;           // 0..3 (m block of 32)
    const int wn   = wid & 1;            // 0..1 (n block of 64)
    const int m0 = blockIdx.x * 128;
    const int n0 = blockIdx.y * 128;
    const uint32_t sbase = smem_u32(dsm);

    float acc[2][8][4];
#pragma unroll
    for (int i = 0; i < 2; ++i)
#pragma unroll
        for (int j = 0; j < 8; ++j)
#pragma unroll
            for (int q = 0; q < 4; ++q) acc[i][j][q] = 0.0f;

    // chunk loader: 2048 cp16 -> 8 per thread
    auto load_chunk = [&](int c, int buf) {
        const int k0 = c * 32;
        const uint32_t bb = sbase + buf * 32768;
#pragma unroll
        for (int r = 0; r < 8; ++r) {
            int i = tid + r * 256;
            int mat = i >> 9;            // 0=Ah 1=Al 2=Bh 3=Bl
            int j   = i & 511;
            int row = j >> 2;
            int cc  = j & 3;
            const __nv_bfloat16* src;
            if (mat == 0)      src = Ah + (size_t)(m0 + row) * 512 + k0 + cc * 8;
            else if (mat == 1) src = Al + (size_t)(m0 + row) * 512 + k0 + cc * 8;
            else if (mat == 2) src = Bh + (size_t)(n0 + row) * 512 + k0 + cc * 8;
            else               src = Bl + (size_t)(n0 + row) * 512 + k0 + cc * 8;
            cp16(bb + mat * 8192 + swz(row, cc), src);
        }
    };

    load_chunk(0, 0);
    cp_commit();

    // per-lane ldmatrix source coordinates
    const int a_r = (lane & 15);               // row within m16
    const int a_h = lane >> 4;                 // k-half
    const int b_r = (lane & 7) + ((lane >> 4) << 3);   // row within n16
    const int b_h = (lane >> 3) & 1;           // k-half

    for (int c = 0; c < 16; ++c) {
        const int buf = c & 1;
        cp_wait0();
        __syncthreads();
        if (c < 15) { load_chunk(c + 1, buf ^ 1); cp_commit(); }

        const uint32_t bb = sbase + buf * 32768;
#pragma unroll
        for (int s = 0; s < 2; ++s) {
            uint32_t a[2][4], bH[4][4], bL[4][4];
            // A-hi fragments (2 m16 tiles)
#pragma unroll
            for (int mt = 0; mt < 2; ++mt) {
                int r = wm * 32 + mt * 16 + a_r;
                ldm4(a[mt], bb + 0 * 8192 + swz(r, s * 2 + a_h));
            }
            // B fragments (4 n16 groups = 8 n8 tiles)
#pragma unroll
            for (int g = 0; g < 4; ++g) {
                int r = wn * 64 + g * 16 + b_r;
                ldm4(bH[g], bb + 2 * 8192 + swz(r, s * 2 + b_h));
                ldm4(bL[g], bb + 3 * 8192 + swz(r, s * 2 + b_h));
            }
            // Ah*Bh, Ah*Bl
#pragma unroll
            for (int mt = 0; mt < 2; ++mt)
#pragma unroll
                for (int g = 0; g < 4; ++g) {
                    mma16816(acc[mt][g * 2],     a[mt], bH[g][0], bH[g][1]);
                    mma16816(acc[mt][g * 2 + 1], a[mt], bH[g][2], bH[g][3]);
                }
#pragma unroll
            for (int mt = 0; mt < 2; ++mt)
#pragma unroll
                for (int g = 0; g < 4; ++g) {
                    mma16816(acc[mt][g * 2],     a[mt], bL[g][0], bL[g][1]);
                    mma16816(acc[mt][g * 2 + 1], a[mt], bL[g][2], bL[g][3]);
                }
            // A-lo fragments, Al*Bh
#pragma unroll
            for (int mt = 0; mt < 2; ++mt) {
                int r = wm * 32 + mt * 16 + a_r;
                ldm4(a[mt], bb + 1 * 8192 + swz(r, s * 2 + a_h));
            }
#pragma unroll
            for (int mt = 0; mt < 2; ++mt)
#pragma unroll
                for (int g = 0; g < 4; ++g) {
                    mma16816(acc[mt][g * 2],     a[mt], bH[g][0], bH[g][1]);
                    mma16816(acc[mt][g * 2 + 1], a[mt], bH[g][2], bH[g][3]);
                }
        }
    }

    // c2 values for this thread's 16 columns
    float c2v[16];
#pragma unroll
    for (int nt = 0; nt < 8; ++nt)
#pragma unroll
        for (int cb = 0; cb < 2; ++cb)
            c2v[nt * 2 + cb] =
                __ldg(&c2[n0 + wn * 64 + nt * 8 + (lane & 3) * 2 + cb]);

    // epilogue: per-row argmin (4 rows per thread), shfl-reduce across quad
#pragma unroll
    for (int mt = 0; mt < 2; ++mt)
#pragma unroll
        for (int h = 0; h < 2; ++h) {
            u64 best = ~0ull;
#pragma unroll
            for (int nt = 0; nt < 8; ++nt)
#pragma unroll
                for (int cb = 0; cb < 2; ++cb) {
                    float s = c2v[nt * 2 + cb] - 2.0f * acc[mt][nt][h * 2 + cb];
                    int n = n0 + wn * 64 + nt * 8 + (lane & 3) * 2 + cb;
                    u64 k = dist_key(s, n);
                    if (k < best) best = k;
                }
            u64 o1 = __shfl_xor_sync(0xffffffffu, best, 1);
            if (o1 < best) best = o1;
            u64 o2 = __shfl_xor_sync(0xffffffffu, best, 2);
            if (o2 < best) best = o2;
            if ((lane & 3) == 0) {
                int row = wm * 32 + mt * 16 + (lane >> 2) + h * 8;
                sRed[row][wn] = best;
            }
        }
    __syncthreads();

    if (tid < 128) {
        u64 b0 = sRed[tid][0], b1 = sRed[tid][1];
        u64 best = b0 < b1 ? b0 : b1;
        pkey[(size_t)(m0 + tid) * NT + blockIdx.y] = best;
    }
}

// ---------------------------------------------------------------------------
// Finalize: per (b,l) reduce 16 key-partials per codebook -> tokens (float),
// then emb = mean of the 4 embedding rows.
// ---------------------------------------------------------------------------
__global__ void finalize_kernel(const u64* __restrict__ pkey,
                                const float* __restrict__ emb_table,
                                float* __restrict__ out) {
    __shared__ int tok[KCB];
    const int m = blockIdx.x;
    const int b = m >> 12, l = m & 4095;
    const int tid = threadIdx.x;

    if (tid < KCB) {
        u64 best = ~0ull;
#pragma unroll
        for (int j = 0; j < 16; ++j) {
            u64 v = pkey[(size_t)m * NT + tid * 16 + j];
            if (v < best) best = v;
        }
        int t = ((int)(best & 0xffffffffu)) & (VOCAB - 1);
        tok[tid] = t;
        out[((size_t)b * KCB + tid) * L3O + l] = (float)t;
    }
    __syncthreads();

    float* out_emb = out + (size_t)NB * KCB * L3O;
    int t0 = tok[0], t1 = tok[1], t2 = tok[2], t3 = tok[3];
    for (int h = tid; h < 512; h += 128) {
        float s = emb_table[(size_t)t0 * 512 + h] + emb_table[(size_t)t1 * 512 + h]
                + emb_table[(size_t)t2 * 512 + h] + emb_table[(size_t)t3 * 512 + h];
        out_emb[((size_t)b * L3O + l) * 512 + h] = 0.25f * s;
    }
}

// ---------------------------------------------------------------------------
extern "C" void kernel_launch(void* const* d_in, const int* in_sizes, int n_in,
                              void* d_out, int out_size) {
    const float* audio = (const float*)d_in[0];
    const float* w1    = (const float*)d_in[1];
    const float* b1    = (const float*)d_in[2];
    const float* w2    = (const float*)d_in[3];
    const float* b2    = (const float*)d_in[4];
    const float* w3    = (const float*)d_in[5];
    const float* b3    = (const float*)d_in[6];
    const float* cb    = (const float*)d_in[7];
    const float* emb   = (const float*)d_in[8];
    float* out = (float*)d_out;

    float *f1p, *f2p, *f3, *w2t, *w3t, *c2p;
    __nv_bfloat16 *ah, *al, *bh, *bl;
    u64* pkey;
    cudaGetSymbolAddress((void**)&f1p,  g_f1p);
    cudaGetSymbolAddress((void**)&f2p,  g_f2p);
    cudaGetSymbolAddress((void**)&f3,   g_f3);
    cudaGetSymbolAddress((void**)&w2t,  g_w2t);
    cudaGetSymbolAddress((void**)&w3t,  g_w3t);
    cudaGetSymbolAddress((void**)&ah,   g_Ah);
    cudaGetSymbolAddress((void**)&al,   g_Al);
    cudaGetSymbolAddress((void**)&bh,   g_Bh);
    cudaGetSymbolAddress((void**)&bl,   g_Bl);
    cudaGetSymbolAddress((void**)&c2p,  g_c2);
    cudaGetSymbolAddress((void**)&pkey, g_pkey);

    // prep
    guard_zero<<<((NB * C1 + NB * C2C) * 16 + 255) / 256, 256>>>(f1p, f2p);
    transpose_w<<<(C2C * C1 * 7 + 255) / 256, 256>>>(w2, w2t, C2C, C1);
    transpose_w<<<(C3 * C2C * 7 + 255) / 256, 256>>>(w3, w3t, C3, C2C);
    c2_kernel<<<NCODES / 8, 256>>>(cb, c2p);
    split_B<<<(NCODES * 512 + 255) / 256, 256>>>(cb, bh, bl);

    // conv chain
    conv1_kernel<<<dim3(L1O / 256, C1, NB), 256>>>(audio, w1, b1, f1p);
    conv_tiled<C1><<<dim3(L2O / 128, C2C / 128, NB), 256>>>(
        f1p, w2t, b2, f2p, L1O, L2O, C2C, 1, L2O + 16, 8);
    conv_tiled<C2C><<<dim3(L3O / 128, C3 / 128, NB), 256>>>(
        f2p, w3t, b3, f3, L2O, L3O, C3, 0, L3O, 0);

    // feats split + transpose
    split_A<<<dim3(512 / 32, L3O / 32, NB), dim3(32, 8)>>>(f3, ah, al);

    // mma.sync VQ GEMM + argmin (64 KB dynamic smem)
    cudaFuncSetAttribute(vq_mma, cudaFuncAttributeMaxDynamicSharedMemorySize, 65536);
    vq_mma<<<dim3(MTOT / 128, NCODES / 128), 256, 65536>>>(
        ah, al, bh, bl, c2p, pkey);

    finalize_kernel<<<MTOT, 128>>>(pkey, emb, out);
}

// round 8
// speedup vs baseline: 3.0846x; 1.4649x over previous
#include <cuda_runtime.h>
#include <cuda_bf16.h>
#include <cstdint>

// Problem constants
#define NB 4
#define SLEN 32768
#define C1 128
#define C2C 256
#define C3 512
#define L1O 16384
#define L2O 8192
#define L3O 4096
#define VOCAB 2048
#define KCB 4
#define NCODES (KCB * VOCAB)   // 8192
#define MTOT (NB * L3O)        // 16384
#define NT 64                  // 8192/128 n-tiles, 16 per codebook

typedef unsigned long long u64;

// bf16 split activations, transposed: X [b][pos][CI], 4 guard rows each side.
__device__ ulonglong2 g_X1h[NB * (L1O + 8) * C1 / 8];
__device__ ulonglong2 g_X1l[NB * (L1O + 8) * C1 / 8];
__device__ ulonglong2 g_X2h[NB * (L2O + 8) * C2C / 8];
__device__ ulonglong2 g_X2l[NB * (L2O + 8) * C2C / 8];
// split weights [7][CO][CI]
__device__ ulonglong2 g_W2h[7 * C2C * C1 / 8];
__device__ ulonglong2 g_W2l[7 * C2C * C1 / 8];
__device__ ulonglong2 g_W3h[7 * C3 * C2C / 8];
__device__ ulonglong2 g_W3l[7 * C3 * C2C / 8];
// vq operands
__device__ ulonglong2 g_Ah[MTOT * 512 / 8];      // feats hi  [m][k] (conv3 output)
__device__ ulonglong2 g_Al[MTOT * 512 / 8];
__device__ ulonglong2 g_Bh[NCODES * 512 / 8];    // codes hi  [n][k]
__device__ ulonglong2 g_Bl[NCODES * 512 / 8];
__device__ float g_c2[NCODES];
__device__ u64   g_pkey[MTOT * NT];

// ---------------------------------------------------------------------------
// helpers
// ---------------------------------------------------------------------------
__device__ __forceinline__ void cp16(uint32_t dst, const void* src) {
    asm volatile("cp.async.cg.shared.global [%0], [%1], 16;" :: "r"(dst), "l"(src));
}
__device__ __forceinline__ void cp_commit() { asm volatile("cp.async.commit_group;"); }
__device__ __forceinline__ void cp_wait0()  { asm volatile("cp.async.wait_group 0;"); }

__device__ __forceinline__ uint32_t smem_u32(const void* p) {
    return (uint32_t)__cvta_generic_to_shared(p);
}

__device__ __forceinline__ u64 dist_key(float v, int n) {
    unsigned int fb = __float_as_uint(v);
    fb = (fb & 0x80000000u) ? ~fb : (fb | 0x80000000u);
    return ((u64)fb << 32) | (unsigned int)n;
}

__device__ __forceinline__ void ldm4(uint32_t* r, uint32_t addr) {
    asm volatile("ldmatrix.sync.aligned.m8n8.x4.shared.b16 {%0,%1,%2,%3}, [%4];"
                 : "=r"(r[0]), "=r"(r[1]), "=r"(r[2]), "=r"(r[3]) : "r"(addr));
}
__device__ __forceinline__ void mma16816(float* c, const uint32_t* a,
                                         uint32_t b0, uint32_t b1) {
    asm volatile(
        "mma.sync.aligned.m16n8k16.row.col.f32.bf16.bf16.f32 "
        "{%0,%1,%2,%3}, {%4,%5,%6,%7}, {%8,%9}, {%0,%1,%2,%3};"
        : "+f"(c[0]), "+f"(c[1]), "+f"(c[2]), "+f"(c[3])
        : "r"(a[0]), "r"(a[1]), "r"(a[2]), "r"(a[3]), "r"(b0), "r"(b1));
}

// vq smem swizzle (rows of 64 B = 4 chunks)
__device__ __forceinline__ int swz(int row, int c) {
    return row * 64 + ((c ^ ((row & 3) ^ ((row >> 2) & 1))) << 4);
}
// conv smem swizzle for 32 B rows (2 chunks): s = parity of low 3 row bits
__device__ __forceinline__ int s3(int row) {
    return (row ^ (row >> 1) ^ (row >> 2)) & 1;
}

// ---------------------------------------------------------------------------
// guard zeroing: X1/X2 guard rows (4 each side)
// ---------------------------------------------------------------------------
__global__ void guard_zero(uint32_t* x1h, uint32_t* x1l,
                           uint32_t* x2h, uint32_t* x2l) {
    int i = blockIdx.x * 256 + threadIdx.x;
    if (i < 4096) {                       // X1: 2 halves x 2048 u32
        int half = i >> 11, j = i & 2047;
        int b = j >> 9, r = (j >> 6) & 7, w = j & 63;
        int row = (r < 4) ? r : (L1O + r);
        uint32_t* p = half ? x1l : x1h;
        p[(size_t)(b * (L1O + 8) + row) * 64 + w] = 0u;
    } else if (i < 4096 + 8192) {         // X2: 2 halves x 4096 u32
        int j = i - 4096;
        int half = j >> 12; j &= 4095;
        int b = j >> 10, r = (j >> 7) & 7, w = j & 127;
        int row = (r < 4) ? r : (L2O + r);
        uint32_t* p = half ? x2l : x2h;
        p[(size_t)(b * (L2O + 8) + row) * 128 + w] = 0u;
    }
}

// ---------------------------------------------------------------------------
// split weights: w [CO][CI][7] fp32 -> Wh/Wl [7][CO][CI] bf16
// ---------------------------------------------------------------------------
__global__ void split_W(const float* __restrict__ w,
                        __nv_bfloat16* __restrict__ wh,
                        __nv_bfloat16* __restrict__ wl, int CO, int CI) {
    int i = blockIdx.x * 256 + threadIdx.x;
    if (i >= CO * CI * 7) return;
    int co = i / (CI * 7);
    int r  = i % (CI * 7);
    int ci = r / 7, t = r % 7;
    float v = w[i];
    __nv_bfloat16 h = __float2bfloat16(v);
    wh[((size_t)t * CO + co) * CI + ci] = h;
    wl[((size_t)t * CO + co) * CI + ci] = __float2bfloat16(v - __bfloat162float(h));
}

// ---------------------------------------------------------------------------
// conv1: [B,1,32768] -> relu -> X1 [b][pos][128] bf16 hi/lo (offset 4 rows)
// ---------------------------------------------------------------------------
__global__ void conv1_kernel(const float* __restrict__ x,
                             const float* __restrict__ w,
                             const float* __restrict__ bias,
                             __nv_bfloat16* __restrict__ yh,
                             __nv_bfloat16* __restrict__ yl) {
    int tid = threadIdx.x;
    int co = tid & 127;
    int l  = blockIdx.x * 2 + (tid >> 7);
    int b  = blockIdx.z;
    const float* xb = x + b * SLEN;
    float acc = bias[co];
#pragma unroll
    for (int t = 0; t < 7; ++t) {
        int g = 2 * l + t - 3;
        float xv = (g >= 0 && g < SLEN) ? xb[g] : 0.0f;
        acc = fmaf(w[co * 7 + t], xv, acc);
    }
    acc = fmaxf(acc, 0.0f);
    __nv_bfloat16 h = __float2bfloat16(acc);
    size_t o = (size_t)(b * (L1O + 8) + l + 4) * C1 + co;
    yh[o] = h;
    yl[o] = __float2bfloat16(acc - __bfloat162float(h));
}

// ---------------------------------------------------------------------------
// conv via mma.sync bf16 split (hh + hl + lh products).
// m = l (128/block), n = co (128/block), k = ci (chunks of 16), taps t=0..6.
// Parity-split input slabs: for tap t all A rows live in one parity slab
// at consecutive indices e = li + ((t+1)>>1), parity (t+1)&1.
// smem/buffer: slab [2 half][2 par][136 rows][32B] = 17408 B,
//              W    [2 half][7*128 rows][32B]      = 57344 B  -> 74752 B.
// ---------------------------------------------------------------------------
#define SLAB_PAR  4352
#define SLAB_HALF 8704
#define SLAB_SZ   17408
#define W_HALF    28672
#define CBUF      74752

template <int CI>
__global__ __launch_bounds__(256, 1) void conv_mma(
        const __nv_bfloat16* __restrict__ Xh, const __nv_bfloat16* __restrict__ Xl,
        const __nv_bfloat16* __restrict__ Wh, const __nv_bfloat16* __restrict__ Wl,
        const float* __restrict__ bias,
        __nv_bfloat16* __restrict__ Yh, __nv_bfloat16* __restrict__ Yl,
        int L_in, int L_out, int CO, int do_relu, int y_pad, int y_off) {
    extern __shared__ __align__(16) char dsm[];
    const uint32_t sbase = smem_u32(dsm);

    const int tid  = threadIdx.x;
    const int lane = tid & 31;
    const int wid  = tid >> 5;
    const int wm   = wid >> 1;          // 0..3: l block of 32
    const int wn   = wid & 1;           // 0..1: co block of 64
    const int l0  = blockIdx.x * 128;
    const int co0 = blockIdx.y * 128;
    const int b   = blockIdx.z;

    float acc[2][8][4];
#pragma unroll
    for (int i = 0; i < 2; ++i)
#pragma unroll
        for (int j = 0; j < 8; ++j)
#pragma unroll
            for (int q = 0; q < 4; ++q) acc[i][j][q] = 0.0f;

    // loaders for k-chunk (16 ci starting at ci0 = ch*16)
    auto load_chunk = [&](int ch, int buf) {
        const int ci0 = ch * 16;
        const uint32_t bb = sbase + buf * CBUF;
        // slab: rel 0..261, 2 halves, 2 chunks
        for (int i = tid; i < 262 * 4; i += 256) {
            int rel = i >> 2;
            int half = (i >> 1) & 1, ck = i & 1;
            int e = rel >> 1, par = rel & 1;
            const __nv_bfloat16* src = (half ? Xl : Xh) +
                (size_t)(b * (L_in + 8) + 2 * l0 + rel) * CI + ci0 + ck * 8;
            cp16(bb + half * SLAB_HALF + par * SLAB_PAR + e * 32 +
                 ((ck ^ s3(e)) << 4), src);
        }
        // W: rows (t,co) 0..895, 2 halves, 2 chunks
#pragma unroll
        for (int r = 0; r < 14; ++r) {
            int i = tid + r * 256;
            int row = i >> 2;
            int half = (i >> 1) & 1, ck = i & 1;
            int t = row >> 7, col = row & 127;
            const __nv_bfloat16* src = (half ? Wl : Wh) +
                (size_t)(t * CO + co0 + col) * CI + ci0 + ck * 8;
            cp16(bb + SLAB_SZ + half * W_HALF + row * 32 +
                 ((ck ^ s3(row)) << 4), src);
        }
    };

    load_chunk(0, 0);
    cp_commit();

    const int a_r = lane & 15;                        // A row within m16
    const int a_h = lane >> 4;                        // A k8 chunk
    const int b_r = (lane & 7) + ((lane >> 4) << 3);  // B row within n16
    const int b_h = (lane >> 3) & 1;                  // B k8 chunk

    const int NCH = CI / 16;
    for (int ch = 0; ch < NCH; ++ch) {
        const int buf = ch & 1;
        cp_wait0();
        __syncthreads();
        if (ch + 1 < NCH) { load_chunk(ch + 1, buf ^ 1); cp_commit(); }

        const uint32_t bb = sbase + buf * CBUF;
#pragma unroll
        for (int t = 0; t < 7; ++t) {
            const int par = (t + 1) & 1;
            const int shift = (t + 1) >> 1;
            uint32_t aH[2][4], aL[2][4];
#pragma unroll
            for (int mt = 0; mt < 2; ++mt) {
                int e = wm * 32 + mt * 16 + a_r + shift;
                uint32_t sa = bb + par * SLAB_PAR + e * 32 + ((a_h ^ s3(e)) << 4);
                ldm4(aH[mt], sa);
                ldm4(aL[mt], sa + SLAB_HALF);
            }
            uint32_t bH[4][4], bL[4][4];
#pragma unroll
            for (int g = 0; g < 4; ++g) {
                int row = t * 128 + wn * 64 + g * 16 + b_r;
                uint32_t sb = bb + SLAB_SZ + row * 32 + ((b_h ^ s3(row)) << 4);
                ldm4(bH[g], sb);
                ldm4(bL[g], sb + W_HALF);
            }
#pragma unroll
            for (int mt = 0; mt < 2; ++mt)
#pragma unroll
                for (int g = 0; g < 4; ++g) {
                    mma16816(acc[mt][g * 2],     aH[mt], bH[g][0], bH[g][1]);
                    mma16816(acc[mt][g * 2 + 1], aH[mt], bH[g][2], bH[g][3]);
                }
#pragma unroll
            for (int mt = 0; mt < 2; ++mt)
#pragma unroll
                for (int g = 0; g < 4; ++g) {
                    mma16816(acc[mt][g * 2],     aH[mt], bL[g][0], bL[g][1]);
                    mma16816(acc[mt][g * 2 + 1], aH[mt], bL[g][2], bL[g][3]);
                }
#pragma unroll
            for (int mt = 0; mt < 2; ++mt)
#pragma unroll
                for (int g = 0; g < 4; ++g) {
                    mma16816(acc[mt][g * 2],     aL[mt], bH[g][0], bH[g][1]);
                    mma16816(acc[mt][g * 2 + 1], aL[mt], bH[g][2], bH[g][3]);
                }
        }
    }

    // epilogue: bias (+relu), split hi/lo, store to Y [row l][co]
    const size_t ybase = (size_t)b * (L_out + y_pad) + y_off;
#pragma unroll
    for (int mt = 0; mt < 2; ++mt)
#pragma unroll
        for (int j = 0; j < 8; ++j)
#pragma unroll
            for (int h8 = 0; h8 < 2; ++h8) {
                int l = l0 + wm * 32 + mt * 16 + (lane >> 2) + h8 * 8;
                int co = co0 + wn * 64 + j * 8 + (lane & 3) * 2;
                float v0 = acc[mt][j][h8 * 2]     + __ldg(&bias[co]);
                float v1 = acc[mt][j][h8 * 2 + 1] + __ldg(&bias[co + 1]);
                if (do_relu) { v0 = fmaxf(v0, 0.0f); v1 = fmaxf(v1, 0.0f); }
                __nv_bfloat16 h0 = __float2bfloat16(v0);
                __nv_bfloat16 h1 = __float2bfloat16(v1);
                __nv_bfloat162 hp; hp.x = h0; hp.y = h1;
                __nv_bfloat162 lp;
                lp.x = __float2bfloat16(v0 - __bfloat162float(h0));
                lp.y = __float2bfloat16(v1 - __bfloat162float(h1));
                size_t o = (ybase + l) * CO + co;
                *(__nv_bfloat162*)(Yh + o) = hp;
                *(__nv_bfloat162*)(Yl + o) = lp;
            }
}

// ---------------------------------------------------------------------------
// c2[n] = sum_h codebook[n][h]^2 (exact fp32). One warp per row.
// ---------------------------------------------------------------------------
__global__ void c2_kernel(const float* __restrict__ cb, float* __restrict__ c2) {
    int warp = blockIdx.x * 8 + (threadIdx.x >> 5);
    int lane = threadIdx.x & 31;
    if (warp >= NCODES) return;
    const float* row = cb + (size_t)warp * 512;
    float s = 0.0f;
#pragma unroll
    for (int h = lane; h < 512; h += 32) { float v = row[h]; s = fmaf(v, v, s); }
#pragma unroll
    for (int o = 16; o > 0; o >>= 1) s += __shfl_down_sync(0xffffffffu, s, o);
    if (lane == 0) c2[warp] = s;
}

// ---------------------------------------------------------------------------
// split codebook: cb [8192][512] fp32 -> Bh/Bl [n][k] bf16
// ---------------------------------------------------------------------------
__global__ void split_B(const float* __restrict__ cb,
                        __nv_bfloat16* __restrict__ bh,
                        __nv_bfloat16* __restrict__ bl) {
    int i = blockIdx.x * 256 + threadIdx.x;
    if (i >= NCODES * 512) return;
    float v = cb[i];
    __nv_bfloat16 h = __float2bfloat16(v);
    bh[i] = h;
    bl[i] = __float2bfloat16(v - __bfloat162float(h));
}

// ---------------------------------------------------------------------------
// mma.sync VQ GEMM + argmin (unchanged from R6).
// ---------------------------------------------------------------------------
__global__ __launch_bounds__(256, 2) void vq_mma(
        const __nv_bfloat16* __restrict__ Ah, const __nv_bfloat16* __restrict__ Al,
        const __nv_bfloat16* __restrict__ Bh, const __nv_bfloat16* __restrict__ Bl,
        const float* __restrict__ c2, u64* __restrict__ pkey) {
    extern __shared__ __align__(16) char dsm[];          // 2 * 32 KB
    __shared__ u64 sRed[128][2];

    const int tid  = threadIdx.x;
    const int lane = tid & 31;
    const int wid  = tid >> 5;
    const int wm   = wid >> 1;
    const int wn   = wid & 1;
    const int m0 = blockIdx.x * 128;
    const int n0 = blockIdx.y * 128;
    const uint32_t sbase = smem_u32(dsm);

    float acc[2][8][4];
#pragma unroll
    for (int i = 0; i < 2; ++i)
#pragma unroll
        for (int j = 0; j < 8; ++j)
#pragma unroll
            for (int q = 0; q < 4; ++q) acc[i][j][q] = 0.0f;

    auto load_chunk = [&](int c, int buf) {
        const int k0 = c * 32;
        const uint32_t bb = sbase + buf * 32768;
#pragma unroll
        for (int r = 0; r < 8; ++r) {
            int i = tid + r * 256;
            int mat = i >> 9;
            int j   = i & 511;
            int row = j >> 2;
            int cc  = j & 3;
            const __nv_bfloat16* src;
            if (mat == 0)      src = Ah + (size_t)(m0 + row) * 512 + k0 + cc * 8;
            else if (mat == 1) src = Al + (size_t)(m0 + row) * 512 + k0 + cc * 8;
            else if (mat == 2) src = Bh + (size_t)(n0 + row) * 512 + k0 + cc * 8;
            else               src = Bl + (size_t)(n0 + row) * 512 + k0 + cc * 8;
            cp16(bb + mat * 8192 + swz(row, cc), src);
        }
    };

    load_chunk(0, 0);
    cp_commit();

    const int a_r = (lane & 15);
    const int a_h = lane >> 4;
    const int b_r = (lane & 7) + ((lane >> 4) << 3);
    const int b_h = (lane >> 3) & 1;

    for (int c = 0; c < 16; ++c) {
        const int buf = c & 1;
        cp_wait0();
        __syncthreads();
        if (c < 15) { load_chunk(c + 1, buf ^ 1); cp_commit(); }

        const uint32_t bb = sbase + buf * 32768;
#pragma unroll
        for (int s = 0; s < 2; ++s) {
            uint32_t a[2][4], bH[4][4], bL[4][4];
#pragma unroll
            for (int mt = 0; mt < 2; ++mt) {
                int r = wm * 32 + mt * 16 + a_r;
                ldm4(a[mt], bb + 0 * 8192 + swz(r, s * 2 + a_h));
            }
#pragma unroll
            for (int g = 0; g < 4; ++g) {
                int r = wn * 64 + g * 16 + b_r;
                ldm4(bH[g], bb + 2 * 8192 + swz(r, s * 2 + b_h));
                ldm4(bL[g], bb + 3 * 8192 + swz(r, s * 2 + b_h));
            }
#pragma unroll
            for (int mt = 0; mt < 2; ++mt)
#pragma unroll
                for (int g = 0; g < 4; ++g) {
                    mma16816(acc[mt][g * 2],     a[mt], bH[g][0], bH[g][1]);
                    mma16816(acc[mt][g * 2 + 1], a[mt], bH[g][2], bH[g][3]);
                }
#pragma unroll
            for (int mt = 0; mt < 2; ++mt)
#pragma unroll
                for (int g = 0; g < 4; ++g) {
                    mma16816(acc[mt][g * 2],     a[mt], bL[g][0], bL[g][1]);
                    mma16816(acc[mt][g * 2 + 1], a[mt], bL[g][2], bL[g][3]);
                }
#pragma unroll
            for (int mt = 0; mt < 2; ++mt) {
                int r = wm * 32 + mt * 16 + a_r;
                ldm4(a[mt], bb + 1 * 8192 + swz(r, s * 2 + a_h));
            }
#pragma unroll
            for (int mt = 0; mt < 2; ++mt)
#pragma unroll
                for (int g = 0; g < 4; ++g) {
                    mma16816(acc[mt][g * 2],     a[mt], bH[g][0], bH[g][1]);
                    mma16816(acc[mt][g * 2 + 1], a[mt], bH[g][2], bH[g][3]);
                }
        }
    }

    float c2v[16];
#pragma unroll
    for (int nt = 0; nt < 8; ++nt)
#pragma unroll
        for (int cb = 0; cb < 2; ++cb)
            c2v[nt * 2 + cb] =
                __ldg(&c2[n0 + wn * 64 + nt * 8 + (lane & 3) * 2 + cb]);

#pragma unroll
    for (int mt = 0; mt < 2; ++mt)
#pragma unroll
        for (int h = 0; h < 2; ++h) {
            u64 best = ~0ull;
#pragma unroll
            for (int nt = 0; nt < 8; ++nt)
#pragma unroll
                for (int cb = 0; cb < 2; ++cb) {
                    float s = c2v[nt * 2 + cb] - 2.0f * acc[mt][nt][h * 2 + cb];
                    int n = n0 + wn * 64 + nt * 8 + (lane & 3) * 2 + cb;
                    u64 k = dist_key(s, n);
                    if (k < best) best = k;
                }
            u64 o1 = __shfl_xor_sync(0xffffffffu, best, 1);
            if (o1 < best) best = o1;
            u64 o2 = __shfl_xor_sync(0xffffffffu, best, 2);
            if (o2 < best) best = o2;
            if ((lane & 3) == 0) {
                int row = wm * 32 + mt * 16 + (lane >> 2) + h * 8;
                sRed[row][wn] = best;
            }
        }
    __syncthreads();

    if (tid < 128) {
        u64 b0 = sRed[tid][0], b1 = sRed[tid][1];
        u64 best = b0 < b1 ? b0 : b1;
        pkey[(size_t)(m0 + tid) * NT + blockIdx.y] = best;
    }
}

// ---------------------------------------------------------------------------
// Finalize: tokens + embedding mean
// ---------------------------------------------------------------------------
__global__ void finalize_kernel(const u64* __restrict__ pkey,
                                const float* __restrict__ emb_table,
                                float* __restrict__ out) {
    __shared__ int tok[KCB];
    const int m = blockIdx.x;
    const int b = m >> 12, l = m & 4095;
    const int tid = threadIdx.x;

    if (tid < KCB) {
        u64 best = ~0ull;
#pragma unroll
        for (int j = 0; j < 16; ++j) {
            u64 v = pkey[(size_t)m * NT + tid * 16 + j];
            if (v < best) best = v;
        }
        int t = ((int)(best & 0xffffffffu)) & (VOCAB - 1);
        tok[tid] = t;
        out[((size_t)b * KCB + tid) * L3O + l] = (float)t;
    }
    __syncthreads();

    float* out_emb = out + (size_t)NB * KCB * L3O;
    int t0 = tok[0], t1 = tok[1], t2 = tok[2], t3 = tok[3];
    for (int h = tid; h < 512; h += 128) {
        float s = emb_table[(size_t)t0 * 512 + h] + emb_table[(size_t)t1 * 512 + h]
                + emb_table[(size_t)t2 * 512 + h] + emb_table[(size_t)t3 * 512 + h];
        out_emb[((size_t)b * L3O + l) * 512 + h] = 0.25f * s;
    }
}

// ---------------------------------------------------------------------------
extern "C" void kernel_launch(void* const* d_in, const int* in_sizes, int n_in,
                              void* d_out, int out_size) {
    const float* audio = (const float*)d_in[0];
    const float* w1    = (const float*)d_in[1];
    const float* b1    = (const float*)d_in[2];
    const float* w2    = (const float*)d_in[3];
    const float* b2    = (const float*)d_in[4];
    const float* w3    = (const float*)d_in[5];
    const float* b3    = (const float*)d_in[6];
    const float* cb    = (const float*)d_in[7];
    const float* emb   = (const float*)d_in[8];
    float* out = (float*)d_out;

    __nv_bfloat16 *x1h, *x1l, *x2h, *x2l, *w2h, *w2l, *w3h, *w3l;
    __nv_bfloat16 *ah, *al, *bh, *bl;
    float* c2p;
    u64* pkey;
    cudaGetSymbolAddress((void**)&x1h, g_X1h);
    cudaGetSymbolAddress((void**)&x1l, g_X1l);
    cudaGetSymbolAddress((void**)&x2h, g_X2h);
    cudaGetSymbolAddress((void**)&x2l, g_X2l);
    cudaGetSymbolAddress((void**)&w2h, g_W2h);
    cudaGetSymbolAddress((void**)&w2l, g_W2l);
    cudaGetSymbolAddress((void**)&w3h, g_W3h);
    cudaGetSymbolAddress((void**)&w3l, g_W3l);
    cudaGetSymbolAddress((void**)&ah,  g_Ah);
    cudaGetSymbolAddress((void**)&al,  g_Al);
    cudaGetSymbolAddress((void**)&bh,  g_Bh);
    cudaGetSymbolAddress((void**)&bl,  g_Bl);
    cudaGetSymbolAddress((void**)&c2p, g_c2);
    cudaGetSymbolAddress((void**)&pkey, g_pkey);

    // prep
    guard_zero<<<(4096 + 8192 + 255) / 256, 256>>>(
        (uint32_t*)x1h, (uint32_t*)x1l, (uint32_t*)x2h, (uint32_t*)x2l);
    split_W<<<(C2C * C1 * 7 + 255) / 256, 256>>>(w2, w2h, w2l, C2C, C1);
    split_W<<<(C3 * C2C * 7 + 255) / 256, 256>>>(w3, w3h, w3l, C3, C2C);
    c2_kernel<<<NCODES / 8, 256>>>(cb, c2p);
    split_B<<<(NCODES * 512 + 255) / 256, 256>>>(cb, bh, bl);

    // conv chain (all tensor-core)
    conv1_kernel<<<dim3(L1O / 2, 1, NB), 256>>>(audio, w1, b1, x1h, x1l);

    cudaFuncSetAttribute(conv_mma<C1>, cudaFuncAttributeMaxDynamicSharedMemorySize,
                         2 * CBUF);
    conv_mma<C1><<<dim3(L2O / 128, C2C / 128, NB), 256, 2 * CBUF>>>(
        x1h, x1l, w2h, w2l, b2, x2h, x2l, L1O, L2O, C2C, 1, 8, 4);

    cudaFuncSetAttribute(conv_mma<C2C>, cudaFuncAttributeMaxDynamicSharedMemorySize,
                         2 * CBUF);
    conv_mma<C2C><<<dim3(L3O / 128, C3 / 128, NB), 256, 2 * CBUF>>>(
        x2h, x2l, w3h, w3l, b3, ah, al, L2O, L3O, C3, 0, 0, 0);

    // vq GEMM + argmin (A comes straight from conv3)
    cudaFuncSetAttribute(vq_mma, cudaFuncAttributeMaxDynamicSharedMemorySize, 65536);
    vq_mma<<<dim3(MTOT / 128, NCODES / 128), 256, 65536>>>(
        ah, al, bh, bl, c2p, pkey);

    finalize_kernel<<<MTOT, 128>>>(pkey, emb, out);
}